// round 1
// baseline (speedup 1.0000x reference)
#include <cuda_runtime.h>
#include <cuda_bf16.h>
#include <cstddef>

#define BB 128
#define TT 1024
#define FF 256
#define UU 8   // prefetch/unroll depth

__device__ __forceinline__ float tanh_approx(float x) {
    float y;
    asm("tanh.approx.f32 %0, %1;" : "=f"(y) : "f"(x));
    return y;
}

__global__ __launch_bounds__(FF, 1)
void grud_fused_kernel(
    const float* __restrict__ input,   // [B, 3, T, F]
    const float* __restrict__ x_mean,
    const float* __restrict__ w_xz, const float* __restrict__ w_hz, const float* __restrict__ w_mz,
    const float* __restrict__ w_xr, const float* __restrict__ w_hr, const float* __restrict__ w_mr,
    const float* __restrict__ w_xh, const float* __restrict__ w_hh, const float* __restrict__ w_mh,
    const float* __restrict__ b_z,  const float* __restrict__ b_r,  const float* __restrict__ b_h,
    const float* __restrict__ W_cls, const float* __restrict__ b_cls,
    float* __restrict__ out)           // [B, 2]
{
    const int b = blockIdx.x;
    const int f = threadIdx.x;

    // Per-feature parameters. Gates use sigmoid(p) = 0.5 + 0.5*tanh(0.5*p),
    // so pre-halve the z/r coefficients (exact up to fp rounding).
    const float xm  = x_mean[f];
    const float wxz = 0.5f * w_xz[f], whz = 0.5f * w_hz[f], wmz = 0.5f * w_mz[f], bz = 0.5f * b_z[f];
    const float wxr = 0.5f * w_xr[f], whr = 0.5f * w_hr[f], wmr = 0.5f * w_mr[f], br = 0.5f * b_r[f];
    const float wxh = w_xh[f],        whh = w_hh[f],        wmh = w_mh[f],        bh = b_h[f];

    // input[b, c, t, f]: X is channel 0, M is channel 1 (D unused -> never read).
    const float* Xp = input + (size_t)b * 3 * TT * FF + f;
    const float* Mp = Xp + (size_t)TT * FF;

    float h = 0.0f;

    // Double-buffered 8-step register prefetch: 16 outstanding coalesced LDGs
    // per warp hide the ~400-600 cyc DRAM latency behind 8*~56 cyc of compute.
    float xb[UU], mb[UU];
#pragma unroll
    for (int u = 0; u < UU; u++) {
        xb[u] = Xp[u * FF];
        mb[u] = Mp[u * FF];
    }

    for (int t0 = 0; t0 < TT; t0 += UU) {
        float xn[UU], mn[UU];
        const int tn = (t0 + UU < TT) ? (t0 + UU) : t0;  // last iter: benign reload
#pragma unroll
        for (int u = 0; u < UU; u++) {
            xn[u] = Xp[(size_t)(tn + u) * FF];
            mn[u] = Mp[(size_t)(tn + u) * FF];
        }

#pragma unroll
        for (int u = 0; u < UU; u++) {
            const float m = mb[u];
            // x <- m*x + (1-m)*x_mean
            const float x = fmaf(m, xb[u] - xm, xm);
            // Everything not depending on h: off the critical chain.
            const float cz = fmaf(wxz, x, fmaf(wmz, m, bz));
            const float cr = fmaf(wxr, x, fmaf(wmr, m, br));
            const float ch = fmaf(wxh, x, fmaf(wmh, m, bh));
            // Critical chain: h -> fma -> tanh -> fma -> blend
            const float zt = tanh_approx(fmaf(whz, h, cz));
            const float rt = tanh_approx(fmaf(whr, h, cr));
            const float r  = fmaf(0.5f, rt, 0.5f);
            const float ht = tanh_approx(fmaf(whh, r * h, ch));
            const float z  = fmaf(0.5f, zt, 0.5f);
            h = fmaf(z, ht - h, h);    // (1-z)*h + z*ht
        }

#pragma unroll
        for (int u = 0; u < UU; u++) { xb[u] = xn[u]; mb[u] = mn[u]; }
    }

    // Fused classifier: out[b,o] = sigmoid(sum_f h[f]*W_cls[o,f] + b_cls[o])
    float p0 = h * W_cls[f];
    float p1 = h * W_cls[FF + f];

#pragma unroll
    for (int o = 16; o > 0; o >>= 1) {
        p0 += __shfl_down_sync(0xffffffffu, p0, o);
        p1 += __shfl_down_sync(0xffffffffu, p1, o);
    }

    __shared__ float s0[FF / 32], s1[FF / 32];
    const int wid = threadIdx.x >> 5;
    const int lid = threadIdx.x & 31;
    if (lid == 0) { s0[wid] = p0; s1[wid] = p1; }
    __syncthreads();

    if (threadIdx.x == 0) {
        float a0 = 0.0f, a1 = 0.0f;
#pragma unroll
        for (int w = 0; w < FF / 32; w++) { a0 += s0[w]; a1 += s1[w]; }
        a0 += b_cls[0];
        a1 += b_cls[1];
        out[b * 2 + 0] = 1.0f / (1.0f + __expf(-a0));
        out[b * 2 + 1] = 1.0f / (1.0f + __expf(-a1));
    }
}

extern "C" void kernel_launch(void* const* d_in, const int* in_sizes, int n_in,
                              void* d_out, int out_size)
{
    const float* input  = (const float*)d_in[0];
    const float* x_mean = (const float*)d_in[1];
    const float* w_xz   = (const float*)d_in[2];
    const float* w_hz   = (const float*)d_in[3];
    const float* w_mz   = (const float*)d_in[4];
    const float* w_xr   = (const float*)d_in[5];
    const float* w_hr   = (const float*)d_in[6];
    const float* w_mr   = (const float*)d_in[7];
    const float* w_xh   = (const float*)d_in[8];
    const float* w_hh   = (const float*)d_in[9];
    const float* w_mh   = (const float*)d_in[10];
    const float* b_z    = (const float*)d_in[11];
    const float* b_r    = (const float*)d_in[12];
    const float* b_h    = (const float*)d_in[13];
    const float* W_cls  = (const float*)d_in[14];
    const float* b_cls  = (const float*)d_in[15];
    float* out = (float*)d_out;

    grud_fused_kernel<<<BB, FF>>>(input, x_mean,
                                  w_xz, w_hz, w_mz,
                                  w_xr, w_hr, w_mr,
                                  w_xh, w_hh, w_mh,
                                  b_z, b_r, b_h,
                                  W_cls, b_cls, out);
}

// round 3
// speedup vs baseline: 1.3580x; 1.3580x over previous
#include <cuda_runtime.h>
#include <cuda_bf16.h>
#include <cstddef>

#define BB  128
#define TT  1024
#define FF  256
#define UU  16    // prefetch ring depth: 32 outstanding LDG.32 per warp
#define TPB 128   // threads per CTA = half a batch's features

// Cross-CTA classifier partials: [b][half][o]  (1 KB, rewritten every run)
__device__ float g_part[BB * 2 * 2];

__device__ __forceinline__ float tanh_approx(float x) {
    float y;
    asm("tanh.approx.f32 %0, %1;" : "=f"(y) : "f"(x));
    return y;
}

__global__ __launch_bounds__(TPB, 2)
void grud_main(
    const float* __restrict__ input,   // [B, 3, T, F]
    const float* __restrict__ x_mean,
    const float* __restrict__ w_xz, const float* __restrict__ w_hz, const float* __restrict__ w_mz,
    const float* __restrict__ w_xr, const float* __restrict__ w_hr, const float* __restrict__ w_mr,
    const float* __restrict__ w_xh, const float* __restrict__ w_hh, const float* __restrict__ w_mh,
    const float* __restrict__ b_z,  const float* __restrict__ b_r,  const float* __restrict__ b_h,
    const float* __restrict__ W_cls)
{
    const int b    = blockIdx.x >> 1;
    const int half = blockIdx.x & 1;
    const int f    = half * TPB + threadIdx.x;

    // sigmoid(p) = 0.5 + 0.5*tanh(0.5*p): pre-halve z/r coefficients.
    const float xm  = x_mean[f];
    const float wxz = 0.5f * w_xz[f], whz = 0.5f * w_hz[f], wmz = 0.5f * w_mz[f], bz = 0.5f * b_z[f];
    const float wxr = 0.5f * w_xr[f], whr = 0.5f * w_hr[f], wmr = 0.5f * w_mr[f], br = 0.5f * b_r[f];
    const float wxh = w_xh[f], wh2 = 0.5f * w_hh[f], wmh = w_mh[f], bh = b_h[f];

    // input[b, c, t, f]: X = channel 0, M = channel 1 (D never read).
    const float* Xp = input + (size_t)b * 3 * TT * FF + f;
    const float* Mp = Xp + (size_t)TT * FF;

    // Prime the 16-deep prefetch ring (32 loads in flight).
    float xb[UU], mb[UU];
#pragma unroll
    for (int u = 0; u < UU; u++) { xb[u] = Xp[u * FF]; mb[u] = Mp[u * FF]; }

    float h = 0.0f;

    for (int t0 = 0; t0 < TT; t0 += UU) {
        // Prefetch base for the tile 16 steps ahead (last tile: warm reload of t=0).
        const int tpre = (t0 + UU < TT) ? (t0 + UU) : 0;
        const float* Xn = Xp + (size_t)tpre * FF;
        const float* Mn = Mp + (size_t)tpre * FF;

#pragma unroll
        for (int u = 0; u < UU; u++) {
            const float xi = xb[u];
            const float m  = mb[u];
            // Refill this ring slot for t0+UU+u; consumed 16 steps (~700 cyc) later.
            xb[u] = Xn[u * FF];
            mb[u] = Mn[u * FF];

            // x <- m*x + (1-m)*x_mean
            const float x  = fmaf(m, xi - xm, xm);
            // Off-chain terms
            const float pz = fmaf(whz, h, fmaf(wxz, x, fmaf(wmz, m, bz)));
            const float pr = fmaf(whr, h, fmaf(wxr, x, fmaf(wmr, m, br)));
            const float ch = fmaf(wxh, x, fmaf(wmh, m, bh));
            const float a  = wh2 * h;                  // 0.5*whh*h
            // Critical chain: fma -> tanh -> fma -> tanh -> fma  (~44 cyc)
            const float tr = tanh_approx(pr);
            const float tz = tanh_approx(pz);
            const float ht = tanh_approx(fmaf(a, tr, a + ch));  // whh*r*h = a + a*tr
            const float z  = fmaf(0.5f, tz, 0.5f);
            const float ng = fmaf(-z, h, h);           // (1-z)*h, off-chain
            h = fmaf(z, ht, ng);
        }
    }

    // Per-CTA classifier partials over this CTA's 128 features.
    float p0 = h * W_cls[f];
    float p1 = h * W_cls[FF + f];
#pragma unroll
    for (int o = 16; o > 0; o >>= 1) {
        p0 += __shfl_down_sync(0xffffffffu, p0, o);
        p1 += __shfl_down_sync(0xffffffffu, p1, o);
    }

    __shared__ float s0[TPB / 32], s1[TPB / 32];
    const int wid = threadIdx.x >> 5;
    if ((threadIdx.x & 31) == 0) { s0[wid] = p0; s1[wid] = p1; }
    __syncthreads();

    if (threadIdx.x == 0) {
        float a0 = 0.0f, a1 = 0.0f;
#pragma unroll
        for (int w = 0; w < TPB / 32; w++) { a0 += s0[w]; a1 += s1[w]; }
        g_part[((b * 2 + half) * 2) + 0] = a0;
        g_part[((b * 2 + half) * 2) + 1] = a1;
    }
}

// Final combine: sum the two halves, add bias, sigmoid. 256 threads = B*OUT.
__global__ void grud_cls(const float* __restrict__ b_cls, float* __restrict__ out)
{
    const int i = threadIdx.x;          // i = b*2 + o
    const int b = i >> 1, o = i & 1;
    const float acc = g_part[(b * 2 + 0) * 2 + o] + g_part[(b * 2 + 1) * 2 + o] + b_cls[o];
    out[i] = 1.0f / (1.0f + __expf(-acc));
}

extern "C" void kernel_launch(void* const* d_in, const int* in_sizes, int n_in,
                              void* d_out, int out_size)
{
    const float* input  = (const float*)d_in[0];
    const float* x_mean = (const float*)d_in[1];
    const float* w_xz   = (const float*)d_in[2];
    const float* w_hz   = (const float*)d_in[3];
    const float* w_mz   = (const float*)d_in[4];
    const float* w_xr   = (const float*)d_in[5];
    const float* w_hr   = (const float*)d_in[6];
    const float* w_mr   = (const float*)d_in[7];
    const float* w_xh   = (const float*)d_in[8];
    const float* w_hh   = (const float*)d_in[9];
    const float* w_mh   = (const float*)d_in[10];
    const float* b_z    = (const float*)d_in[11];
    const float* b_r    = (const float*)d_in[12];
    const float* b_h    = (const float*)d_in[13];
    const float* W_cls  = (const float*)d_in[14];
    const float* b_cls  = (const float*)d_in[15];
    float* out = (float*)d_out;

    grud_main<<<BB * 2, TPB>>>(input, x_mean,
                               w_xz, w_hz, w_mz,
                               w_xr, w_hr, w_mr,
                               w_xh, w_hh, w_mh,
                               b_z, b_r, b_h, W_cls);
    grud_cls<<<1, BB * 2>>>(b_cls, out);
}

// round 5
// speedup vs baseline: 1.8165x; 1.3376x over previous
#include <cuda_runtime.h>
#include <cuda_bf16.h>
#include <cstddef>
#include <cstdint>

#define BB     128
#define TT     1024
#define FF     256
#define TPB    128   // threads per CTA = half a batch's features
#define TS     8     // timesteps per pipeline stage
#define STAGES 4     // smem pipeline depth
#define NSTG   (TT / TS)   // 128 stages

// Cross-CTA classifier partials [b][half][o] and arrival counters [b].
__device__ float g_part[BB * 2 * 2];
__device__ int   g_cnt[BB];   // zero-init; each run returns it to 0

__device__ __forceinline__ float tanh_approx(float x) {
    float y;
    asm("tanh.approx.f32 %0, %1;" : "=f"(y) : "f"(x));
    return y;
}

__device__ __forceinline__ void cp16(uint32_t smem_addr, const void* gptr) {
    asm volatile("cp.async.cg.shared.global [%0], [%1], 16;" :: "r"(smem_addr), "l"(gptr));
}

__global__ __launch_bounds__(TPB, 2)
void grud_main(
    const float* __restrict__ input,   // [B, 3, T, F]
    const float* __restrict__ x_mean,
    const float* __restrict__ w_xz, const float* __restrict__ w_hz, const float* __restrict__ w_mz,
    const float* __restrict__ w_xr, const float* __restrict__ w_hr, const float* __restrict__ w_mr,
    const float* __restrict__ w_xh, const float* __restrict__ w_hh, const float* __restrict__ w_mh,
    const float* __restrict__ b_z,  const float* __restrict__ b_r,  const float* __restrict__ b_h,
    const float* __restrict__ W_cls, const float* __restrict__ b_cls,
    float* __restrict__ out)
{
    // smem tiles: [stage][step][feat]  — X and M planes, 16 KB each.
    __shared__ float sX[STAGES][TS][TPB];
    __shared__ float sM[STAGES][TS][TPB];

    const int b    = blockIdx.x >> 1;
    const int half = blockIdx.x & 1;
    const int f    = half * TPB + threadIdx.x;
    const int tid  = threadIdx.x;

    // sigmoid(p) = 0.5 + 0.5*tanh(0.5*p): pre-halve z/r coefficients.
    const float xm  = x_mean[f];
    const float wxz = 0.5f * w_xz[f], whz = 0.5f * w_hz[f], wmz = 0.5f * w_mz[f], bz = 0.5f * b_z[f];
    const float wxr = 0.5f * w_xr[f], whr = 0.5f * w_hr[f], wmr = 0.5f * w_mr[f], br = 0.5f * b_r[f];
    const float wxh = w_xh[f], wh2 = 0.5f * w_hh[f], wmh = w_mh[f], bh = b_h[f];

    // Global base of this CTA's 512B row segment for channel 0 (X) and 1 (M).
    const float* Xg = input + (size_t)b * 3 * TT * FF + half * TPB;
    const float* Mg = Xg + (size_t)TT * FF;

    // Copy assignment: per stage, 2 ch * 8 rows * 32 chunks(16B) = 512 chunks,
    // 4 per thread; g = tid + i*TPB. ch = g/256, row = (g%256)/32, col16 = g%32.
    auto issue_stage = [&](int s) {
        const int buf = s & (STAGES - 1);
        const int t0  = s * TS;
#pragma unroll
        for (int i = 0; i < 4; i++) {
            const int g   = tid + i * TPB;
            const int ch  = g >> 8;
            const int row = (g & 255) >> 5;
            const int c4  = (g & 31) << 2;           // float index within row
            const float* src = (ch ? Mg : Xg) + (size_t)(t0 + row) * FF + c4;
            float* dst = (ch ? &sM[buf][row][c4] : &sX[buf][row][c4]);
            cp16((uint32_t)__cvta_generic_to_shared(dst), src);
        }
        asm volatile("cp.async.commit_group;");
    };

    // Prologue: fill 3 stages.
    issue_stage(0);
    issue_stage(1);
    issue_stage(2);

    float h = 0.0f;

    for (int s = 0; s < NSTG; s++) {
        const int buf = s & (STAGES - 1);
        asm volatile("cp.async.wait_group 2;");
        __syncthreads();                 // stage s visible to all threads
        if (s + 3 < NSTG) issue_stage(s + 3);   // overwrites buffer of s-1 (safe)

        // Batch the 16 LDS up front, then run 8 recurrence steps.
        float xv[TS], mv[TS];
#pragma unroll
        for (int u = 0; u < TS; u++) { xv[u] = sX[buf][u][tid]; mv[u] = sM[buf][u][tid]; }

#pragma unroll
        for (int u = 0; u < TS; u++) {
            const float m  = mv[u];
            const float x  = fmaf(m, xv[u] - xm, xm);        // m*x + (1-m)*mean
            const float pz = fmaf(whz, h, fmaf(wxz, x, fmaf(wmz, m, bz)));
            const float pr = fmaf(whr, h, fmaf(wxr, x, fmaf(wmr, m, br)));
            const float ch = fmaf(wxh, x, fmaf(wmh, m, bh));
            const float a  = wh2 * h;                        // 0.5*whh*h
            const float tr = tanh_approx(pr);
            const float tz = tanh_approx(pz);
            const float ht = tanh_approx(fmaf(a, tr, a + ch));  // whh*r*h = a + a*tr
            const float z  = fmaf(0.5f, tz, 0.5f);
            const float ng = fmaf(-z, h, h);                 // (1-z)*h
            h = fmaf(z, ht, ng);
        }
        __syncthreads();                 // done reading buf before it is refilled
    }

    // ---- fused classifier ----
    float p0 = h * W_cls[f];
    float p1 = h * W_cls[FF + f];
#pragma unroll
    for (int o = 16; o > 0; o >>= 1) {
        p0 += __shfl_down_sync(0xffffffffu, p0, o);
        p1 += __shfl_down_sync(0xffffffffu, p1, o);
    }

    __shared__ float s0[TPB / 32], s1[TPB / 32];
    const int wid = tid >> 5;
    if ((tid & 31) == 0) { s0[wid] = p0; s1[wid] = p1; }
    __syncthreads();

    if (tid == 0) {
        float a0 = 0.0f, a1 = 0.0f;
#pragma unroll
        for (int w = 0; w < TPB / 32; w++) { a0 += s0[w]; a1 += s1[w]; }
        g_part[(b * 2 + half) * 2 + 0] = a0;
        g_part[(b * 2 + half) * 2 + 1] = a1;
        __threadfence();
        const int old = atomicAdd(&g_cnt[b], 1);
        if (old == 1) {                  // last CTA of this batch pair
            __threadfence();
            const float q0 = g_part[(b * 2) * 2 + 0] + g_part[(b * 2 + 1) * 2 + 0] + b_cls[0];
            const float q1 = g_part[(b * 2) * 2 + 1] + g_part[(b * 2 + 1) * 2 + 1] + b_cls[1];
            out[b * 2 + 0] = 1.0f / (1.0f + __expf(-q0));
            out[b * 2 + 1] = 1.0f / (1.0f + __expf(-q1));
            g_cnt[b] = 0;                // restore for next graph replay
        }
    }
}

extern "C" void kernel_launch(void* const* d_in, const int* in_sizes, int n_in,
                              void* d_out, int out_size)
{
    const float* input  = (const float*)d_in[0];
    const float* x_mean = (const float*)d_in[1];
    const float* w_xz   = (const float*)d_in[2];
    const float* w_hz   = (const float*)d_in[3];
    const float* w_mz   = (const float*)d_in[4];
    const float* w_xr   = (const float*)d_in[5];
    const float* w_hr   = (const float*)d_in[6];
    const float* w_mr   = (const float*)d_in[7];
    const float* w_xh   = (const float*)d_in[8];
    const float* w_hh   = (const float*)d_in[9];
    const float* w_mh   = (const float*)d_in[10];
    const float* b_z    = (const float*)d_in[11];
    const float* b_r    = (const float*)d_in[12];
    const float* b_h    = (const float*)d_in[13];
    const float* W_cls  = (const float*)d_in[14];
    const float* b_cls  = (const float*)d_in[15];
    float* out = (float*)d_out;

    grud_main<<<BB * 2, TPB>>>(input, x_mean,
                               w_xz, w_hz, w_mz,
                               w_xr, w_hr, w_mr,
                               w_xh, w_hh, w_mh,
                               b_z, b_r, b_h,
                               W_cls, b_cls, out);
}